// round 1
// baseline (speedup 1.0000x reference)
#include <cuda_runtime.h>
#include <math.h>

// Problem constants
#define B_    256
#define IC    1152      // in_channels (j)
#define NU_   10        // num_units (n)
#define US    16        // unit_size (u)
#define IU    8         // in_units (i)
#define NUU   160       // NU_*US
#define KTOT  9216      // IU*IC  (contraction index k = i*1152 + j)
#define KSPLIT 36
#define KC    256       // KTOT / KSPLIT

// Scratch (device globals; no runtime allocation)
__device__ float g_Wt[KTOT * NUU];           // W transposed: [k, nu] = W[j,n,u,i], k=i*IC+j
__device__ float g_c[IC * NU_];              // routing coefficients c[j,n]
__device__ float g_logits[IC * NU_];         // routing logits b[j,n]
__device__ float g_Spart[KSPLIT * B_ * NUU]; // split-K partials of s
__device__ float g_V[B_ * NUU];              // v[b,n,u]
__device__ float g_G[NUU * KTOT];            // G[nu, k] = (1/B) * sum_b v[b,nu] x[b,k] (1/B applied later)

// ---------------------------------------------------------------------------
// k_pre: transpose W -> g_Wt, init c = 1/IC (softmax of zero logits), logits=0
// ---------------------------------------------------------------------------
__global__ void k_pre(const float* __restrict__ W) {
    int idx = blockIdx.x * 256 + threadIdx.x;
    if (idx < IC * NU_) { g_c[idx] = 1.0f / (float)IC; g_logits[idx] = 0.0f; }
    if (idx < KTOT * NUU) {
        int k  = idx / NUU;
        int nu = idx - k * NUU;
        int j  = k % IC;
        int i  = k / IC;
        int n  = nu >> 4;
        int u  = nu & 15;
        g_Wt[idx] = W[((j * NU_ + n) * US + u) * IU + i];
    }
}

// ---------------------------------------------------------------------------
// GEMM1: Spart[ks, m, nu] = sum_{k in chunk ks} X[m,k] * (Wt[k,nu] * c[j(k), n(nu)])
// M=256, N=160, K=9216 split into 36 chunks of 256. Grid = 4 Mtiles * 36 = 144.
// ---------------------------------------------------------------------------
__global__ void __launch_bounds__(256) k_gemm1(const float* __restrict__ x) {
    const int mtile = blockIdx.x & 3;
    const int ks    = blockIdx.x >> 2;
    const int m0    = mtile * 64;
    const int kbase = ks * KC;

    __shared__ float Xs[64][33];     // [m][k] padded
    __shared__ float Ws[32][NUU];    // [k][nu], c already applied

    const int tid = threadIdx.x;
    const int ty  = tid >> 4;        // 0..15 (M)
    const int tx  = tid & 15;        // 0..15 (N)

    float acc[4][10];
#pragma unroll
    for (int i = 0; i < 4; i++)
#pragma unroll
        for (int jn = 0; jn < 10; jn++) acc[i][jn] = 0.0f;

    for (int kk = 0; kk < KC; kk += 32) {
        // load X tile: 64x32
#pragma unroll
        for (int r = 0; r < 8; r++) {
            int idx = tid + r * 256;
            int m = idx >> 5, k = idx & 31;
            Xs[m][k] = x[(m0 + m) * KTOT + kbase + kk + k];
        }
        // load W tile (32x160) with c folded in
#pragma unroll
        for (int r = 0; r < 20; r++) {
            int idx = tid + r * 256;
            int kl = idx / NUU;
            int nu = idx - kl * NUU;
            int kg = kbase + kk + kl;
            int j  = kg % IC;
            int n  = nu >> 4;
            Ws[kl][nu] = g_Wt[kg * NUU + nu] * g_c[j * NU_ + n];
        }
        __syncthreads();

#pragma unroll
        for (int k = 0; k < 32; k++) {
            float a[4], bb[10];
#pragma unroll
            for (int i = 0; i < 4; i++) a[i] = Xs[ty * 4 + i][k];
#pragma unroll
            for (int jn = 0; jn < 10; jn++) bb[jn] = Ws[k][tx * 10 + jn];
#pragma unroll
            for (int i = 0; i < 4; i++)
#pragma unroll
                for (int jn = 0; jn < 10; jn++) acc[i][jn] += a[i] * bb[jn];
        }
        __syncthreads();
    }

#pragma unroll
    for (int i = 0; i < 4; i++)
#pragma unroll
        for (int jn = 0; jn < 10; jn++)
            g_Spart[ks * (B_ * NUU) + (m0 + ty * 4 + i) * NUU + tx * 10 + jn] = acc[i][jn];
}

// ---------------------------------------------------------------------------
// Squash: reduce split-K partials -> s[b,nu]; squash over n axis -> v[b,nu].
// Grid 256 blocks (one per b), 160 threads. Optionally writes final output.
// ---------------------------------------------------------------------------
__global__ void k_squash(float* __restrict__ out) {
    const int b = blockIdx.x;
    const int t = threadIdx.x;      // t = n*16 + u
    float s = 0.0f;
#pragma unroll 4
    for (int ks = 0; ks < KSPLIT; ks++)
        s += g_Spart[ks * (B_ * NUU) + b * NUU + t];

    __shared__ float sq[NUU];
    __shared__ float mag[US];
    sq[t] = s * s;
    __syncthreads();
    if (t < US) {
        float m = 0.0f;
#pragma unroll
        for (int n = 0; n < NU_; n++) m += sq[n * US + t];
        mag[t] = m;
    }
    __syncthreads();
    float m = mag[t & 15];
    float v = s * (m / ((1.0f + m) * sqrtf(m)));
    g_V[b * NUU + t] = v;
    if (out) out[b * NUU + t] = v;
}

// ---------------------------------------------------------------------------
// GEMM2: G[nu, k] = sum_b V[b,nu] * X[b,k].  M=160, N=9216, K=256.
// Grid = 144 CTAs over N (64 cols each).
// ---------------------------------------------------------------------------
__global__ void __launch_bounds__(256) k_gemm2(const float* __restrict__ x) {
    const int n0 = blockIdx.x * 64;

    __shared__ float Vs[32][NUU];    // [b][nu]
    __shared__ float Xs[32][64];     // [b][col]

    const int tid = threadIdx.x;
    const int ty  = tid >> 4;        // 0..15 -> 10 rows each
    const int tx  = tid & 15;        // 0..15 -> 4 cols each

    float acc[10][4];
#pragma unroll
    for (int i = 0; i < 10; i++)
#pragma unroll
        for (int jj = 0; jj < 4; jj++) acc[i][jj] = 0.0f;

    for (int kk = 0; kk < B_; kk += 32) {
#pragma unroll
        for (int r = 0; r < 20; r++) {
            int idx = tid + r * 256;
            int bl = idx / NUU;
            int nu = idx - bl * NUU;
            Vs[bl][nu] = g_V[(kk + bl) * NUU + nu];
        }
#pragma unroll
        for (int r = 0; r < 8; r++) {
            int idx = tid + r * 256;
            int bl = idx >> 6, c = idx & 63;
            Xs[bl][c] = x[(kk + bl) * KTOT + n0 + c];
        }
        __syncthreads();

#pragma unroll
        for (int k = 0; k < 32; k++) {
            float a[10], bb[4];
#pragma unroll
            for (int i = 0; i < 10; i++) a[i] = Vs[k][ty * 10 + i];
#pragma unroll
            for (int jj = 0; jj < 4; jj++) bb[jj] = Xs[k][tx * 4 + jj];
#pragma unroll
            for (int i = 0; i < 10; i++)
#pragma unroll
                for (int jj = 0; jj < 4; jj++) acc[i][jj] += a[i] * bb[jj];
        }
        __syncthreads();
    }

#pragma unroll
    for (int i = 0; i < 10; i++)
#pragma unroll
        for (int jj = 0; jj < 4; jj++)
            g_G[(ty * 10 + i) * KTOT + n0 + tx * 4 + jj] = acc[i][jj];
}

// ---------------------------------------------------------------------------
// b-update: logits[j,n] += (1/B) * sum_{i,u} Wt[i*IC+j, n*16+u] * G[n*16+u, i*IC+j]
// Grid 1152 blocks (one per j), 128 threads = (i 0..7) x (u 0..15).
// ---------------------------------------------------------------------------
__global__ void k_bupdate() {
    const int j = blockIdx.x;
    const int t = threadIdx.x;       // 0..127
    const int i = t >> 4;
    const int u = t & 15;
    const int k = i * IC + j;

    float part[NU_];
#pragma unroll
    for (int n = 0; n < NU_; n++) {
        float w = g_Wt[k * NUU + n * US + u];
        float g = g_G[(n * US + u) * KTOT + k];
        part[n] = w * g;
    }
#pragma unroll
    for (int off = 16; off; off >>= 1)
#pragma unroll
        for (int n = 0; n < NU_; n++)
            part[n] += __shfl_down_sync(0xffffffffu, part[n], off);

    __shared__ float red[NU_][4];
    int warp = t >> 5, lane = t & 31;
    if (lane == 0)
#pragma unroll
        for (int n = 0; n < NU_; n++) red[n][warp] = part[n];
    __syncthreads();
    if (t < NU_) {
        float d = red[t][0] + red[t][1] + red[t][2] + red[t][3];
        g_logits[j * NU_ + t] += d * (1.0f / (float)B_);
    }
}

// ---------------------------------------------------------------------------
// Softmax over j (axis 0) for each n. 1 block, 10 warps (one per n).
// ---------------------------------------------------------------------------
__global__ void k_softmax() {
    const int t = threadIdx.x;       // 0..319
    const int n = t >> 5;
    const int lane = t & 31;

    float vals[36];
    float mx = -1e30f;
#pragma unroll
    for (int it = 0; it < 36; it++) {
        int j = lane + it * 32;
        vals[it] = g_logits[j * NU_ + n];
        mx = fmaxf(mx, vals[it]);
    }
#pragma unroll
    for (int off = 16; off; off >>= 1)
        mx = fmaxf(mx, __shfl_xor_sync(0xffffffffu, mx, off));
    float sum = 0.0f;
#pragma unroll
    for (int it = 0; it < 36; it++) { vals[it] = expf(vals[it] - mx); sum += vals[it]; }
#pragma unroll
    for (int off = 16; off; off >>= 1)
        sum += __shfl_xor_sync(0xffffffffu, sum, off);
    float inv = 1.0f / sum;
#pragma unroll
    for (int it = 0; it < 36; it++) {
        int j = lane + it * 32;
        g_c[j * NU_ + n] = vals[it] * inv;
    }
}

// ---------------------------------------------------------------------------
// Launch: 13 graph nodes.
// ---------------------------------------------------------------------------
extern "C" void kernel_launch(void* const* d_in, const int* in_sizes, int n_in,
                              void* d_out, int out_size) {
    const float* x = (const float*)d_in[0];   // [256, 8, 1152] == [256, 9216]
    const float* W = (const float*)d_in[1];   // [1152, 10, 16, 8]
    float* out = (float*)d_out;               // [256, 10, 16, 1]

    k_pre<<<(KTOT * NUU + 255) / 256, 256>>>(W);

    // iter 0 (c uniform from k_pre)
    k_gemm1<<<4 * KSPLIT, 256>>>(x);
    k_squash<<<B_, NUU>>>(nullptr);
    k_gemm2<<<KTOT / 64, 256>>>(x);
    k_bupdate<<<IC, 128>>>();
    k_softmax<<<1, 320>>>();

    // iter 1
    k_gemm1<<<4 * KSPLIT, 256>>>(x);
    k_squash<<<B_, NUU>>>(nullptr);
    k_gemm2<<<KTOT / 64, 256>>>(x);
    k_bupdate<<<IC, 128>>>();
    k_softmax<<<1, 320>>>();

    // iter 2 (final; no logit update needed)
    k_gemm1<<<4 * KSPLIT, 256>>>(x);
    k_squash<<<B_, NUU>>>(out);
}

// round 3
// speedup vs baseline: 1.5717x; 1.5717x over previous
#include <cuda_runtime.h>
#include <cuda_bf16.h>
#include <math.h>
#include <stdint.h>

// Problem constants
#define B_    256
#define IC    1152
#define NU_   10
#define US    16
#define IU    8
#define NUU   160       // NU_*US
#define KTOT  9216      // IU*IC
#define KSPLIT 36
#define SA    72        // smem row stride (bf16 elems): 36 words => bank stride 4 mod 32

// ---------------- device scratch ----------------
__device__ __nv_bfloat16 g_xh [B_ * KTOT];    // x hi, [b][k]
__device__ __nv_bfloat16 g_xl [B_ * KTOT];    // x lo
__device__ __nv_bfloat16 g_xth[KTOT * B_];    // x hi transposed [k][b]
__device__ __nv_bfloat16 g_xtl[KTOT * B_];
__device__ float g_Wnk[NUU * KTOT];           // W fp32 [nu][k]
__device__ float g_Wkn[KTOT * NUU];           // W fp32 [k][nu]
__device__ __nv_bfloat16 g_SWth[NUU * KTOT];  // c-scaled W hi [nu][k]
__device__ __nv_bfloat16 g_SWtl[NUU * KTOT];
__device__ __nv_bfloat16 g_Vth[NUU * B_];     // V^T hi [nu][b]
__device__ __nv_bfloat16 g_Vtl[NUU * B_];
__device__ float g_Spart[KSPLIT * B_ * NUU];
__device__ float g_Gkn[KTOT * NUU];           // G[k][nu] = sum_b x[b,k] v[b,nu]
__device__ float g_logits[IC * NU_];          // [j][n]
__device__ float g_ct[NU_ * IC];              // c transposed [n][j]

// ---------------- HMMA ----------------
__device__ __forceinline__ void mma16816(float* c, const uint32_t* a, const uint32_t* b) {
    asm volatile("mma.sync.aligned.m16n8k16.row.col.f32.bf16.bf16.f32 "
        "{%0,%1,%2,%3}, {%4,%5,%6,%7}, {%8,%9}, {%0,%1,%2,%3};"
        : "+f"(c[0]), "+f"(c[1]), "+f"(c[2]), "+f"(c[3])
        : "r"(a[0]), "r"(a[1]), "r"(a[2]), "r"(a[3]), "r"(b[0]), "r"(b[1]));
}

// ---------------------------------------------------------------------------
// k_prex: split x -> bf16 hi/lo, row-major and transposed. grid (144,4)x256
// ---------------------------------------------------------------------------
__global__ void k_prex(const float* __restrict__ x) {
    __shared__ unsigned sh[64][65];
    const int k0 = blockIdx.x * 64, b0 = blockIdx.y * 64;
    const int tid = threadIdx.x;
#pragma unroll
    for (int i = 0; i < 16; i++) {
        int idx = tid + i * 256;
        int r = idx >> 6, c = idx & 63;
        size_t g = (size_t)(b0 + r) * KTOT + k0 + c;
        float v = x[g];
        __nv_bfloat16 h = __float2bfloat16_rn(v);
        __nv_bfloat16 l = __float2bfloat16_rn(v - __bfloat162float(h));
        g_xh[g] = h; g_xl[g] = l;
        sh[r][c] = ((unsigned)__bfloat16_as_ushort(l) << 16) | (unsigned)__bfloat16_as_ushort(h);
    }
    __syncthreads();
#pragma unroll
    for (int i = 0; i < 16; i++) {
        int idx = tid + i * 256;
        int rr = idx >> 6, cc = idx & 63;
        unsigned p = sh[cc][rr];
        size_t g = (size_t)(k0 + rr) * B_ + b0 + cc;
        g_xth[g] = __ushort_as_bfloat16((unsigned short)(p & 0xFFFF));
        g_xtl[g] = __ushort_as_bfloat16((unsigned short)(p >> 16));
    }
}

// ---------------------------------------------------------------------------
// k_pre_w: W[j,n,u,i] -> Wnk[nu][k], Wkn[k][nu]; init logits/ct. grid 144x256
// ---------------------------------------------------------------------------
__global__ void k_pre_w(const float* __restrict__ W) {
    __shared__ float sm[8 * 1281];
    const int j0 = blockIdx.x * 8;
    const int tid = threadIdx.x;
#pragma unroll
    for (int i = 0; i < 40; i++) {
        int idx = tid + i * 256;
        int jl = idx / 1280, rem = idx - jl * 1280;
        sm[jl * 1281 + rem] = W[(size_t)(j0 + jl) * 1280 + rem];
    }
    __syncthreads();
#pragma unroll
    for (int t = 0; t < 40; t++) {
        int idx = tid + t * 256;                 // = nu*64 + ii*8 + jl
        int jl = idx & 7, ii = (idx >> 3) & 7, nu = idx >> 6;
        g_Wnk[(size_t)nu * KTOT + ii * IC + j0 + jl] = sm[jl * 1281 + nu * 8 + ii];
    }
#pragma unroll
    for (int t = 0; t < 40; t++) {
        int idx = tid + t * 256;                 // = (ii*8 + jl)*160 + nu
        int nu = idx % 160, rest = idx / 160;
        int jl = rest & 7, ii = rest >> 3;
        g_Wkn[(size_t)(ii * IC + j0 + jl) * NUU + nu] = sm[jl * 1281 + nu * 8 + ii];
    }
    int gidx = blockIdx.x * 256 + tid;
    if (gidx < IC * NU_) { g_logits[gidx] = 0.0f; g_ct[gidx] = 1.0f / (float)IC; }
}

// ---------------------------------------------------------------------------
// k_scale: SWt_{hi,lo}[nu][k] = split(Wnk[nu][k] * c[n][j]). grid 160x256
// ---------------------------------------------------------------------------
__global__ void k_scale() {
    __shared__ float cs[IC];
    const int nu = blockIdx.x;
    const int n = nu >> 4;
    const int tid = threadIdx.x;
    for (int t = tid; t < IC; t += 256) cs[t] = g_ct[n * IC + t];
    __syncthreads();
#pragma unroll
    for (int i = 0; i < 9; i++) {
        int e4 = tid + i * 256;
        int k = e4 * 4;
        int j = k % IC;
        float4 w = *reinterpret_cast<const float4*>(g_Wnk + (size_t)nu * KTOT + k);
        float v0 = w.x * cs[j], v1 = w.y * cs[j + 1], v2 = w.z * cs[j + 2], v3 = w.w * cs[j + 3];
        __nv_bfloat16 h0 = __float2bfloat16_rn(v0), h1 = __float2bfloat16_rn(v1);
        __nv_bfloat16 h2 = __float2bfloat16_rn(v2), h3 = __float2bfloat16_rn(v3);
        __nv_bfloat16 l0 = __float2bfloat16_rn(v0 - __bfloat162float(h0));
        __nv_bfloat16 l1 = __float2bfloat16_rn(v1 - __bfloat162float(h1));
        __nv_bfloat16 l2 = __float2bfloat16_rn(v2 - __bfloat162float(h2));
        __nv_bfloat16 l3 = __float2bfloat16_rn(v3 - __bfloat162float(h3));
        uint2 ph, pl;
        ph.x = ((unsigned)__bfloat16_as_ushort(h1) << 16) | __bfloat16_as_ushort(h0);
        ph.y = ((unsigned)__bfloat16_as_ushort(h3) << 16) | __bfloat16_as_ushort(h2);
        pl.x = ((unsigned)__bfloat16_as_ushort(l1) << 16) | __bfloat16_as_ushort(l0);
        pl.y = ((unsigned)__bfloat16_as_ushort(l3) << 16) | __bfloat16_as_ushort(l2);
        *reinterpret_cast<uint2*>(g_SWth + (size_t)nu * KTOT + k) = ph;
        *reinterpret_cast<uint2*>(g_SWtl + (size_t)nu * KTOT + k) = pl;
    }
}

// ---------------------------------------------------------------------------
// GEMM1 (HMMA): Spart[ks][m=b(64/tile)][nu] = X * (c.W)^T  over k-chunk of 256.
// grid 144 (= mt 0..3 x ks 0..35), 256 threads (8 warps: wm 0..3, wn 0..1).
// ---------------------------------------------------------------------------
#define G1_SMEM ((64*SA*2 + 160*SA*2) * 2)   // A hi/lo + B hi/lo bytes = 64512

__global__ void __launch_bounds__(256) k_hmma1() {
    extern __shared__ __nv_bfloat16 sm[];
    __nv_bfloat16* sAh = sm;
    __nv_bfloat16* sAl = sAh + 64 * SA;
    __nv_bfloat16* sBh = sAl + 64 * SA;
    __nv_bfloat16* sBl = sBh + 160 * SA;

    const int mt = blockIdx.x & 3, ks = blockIdx.x >> 2;
    const int m0 = mt * 64, kbase = ks * 256;
    const int tid = threadIdx.x;
    const int warp = tid >> 5, lane = tid & 31;
    const int wm = warp & 3, wn = warp >> 2;
    const int lg = lane >> 2, lt = lane & 3;

    float acc[10][4];
#pragma unroll
    for (int f = 0; f < 10; f++)
#pragma unroll
        for (int q = 0; q < 4; q++) acc[f][q] = 0.0f;

    for (int c4 = 0; c4 < 4; ++c4) {
        const int col = kbase + c4 * 64;
        // load A (64 x 64) hi/lo
#pragma unroll
        for (int t = 0; t < 2; t++) {
            int idx = tid + t * 256;
            int r = idx >> 3, q = idx & 7;
            const size_t g = (size_t)(m0 + r) * KTOT + col + q * 8;
            *reinterpret_cast<uint4*>(sAh + r * SA + q * 8) = *reinterpret_cast<const uint4*>(g_xh + g);
            *reinterpret_cast<uint4*>(sAl + r * SA + q * 8) = *reinterpret_cast<const uint4*>(g_xl + g);
        }
        // load B (160 x 64) hi/lo
#pragma unroll
        for (int t = 0; t < 5; t++) {
            int idx = tid + t * 256;
            int r = idx >> 3, q = idx & 7;
            const size_t g = (size_t)r * KTOT + col + q * 8;
            *reinterpret_cast<uint4*>(sBh + r * SA + q * 8) = *reinterpret_cast<const uint4*>(g_SWth + g);
            *reinterpret_cast<uint4*>(sBl + r * SA + q * 8) = *reinterpret_cast<const uint4*>(g_SWtl + g);
        }
        __syncthreads();

#pragma unroll
        for (int kk = 0; kk < 4; kk++) {
            const int kb = kk * 16;
            uint32_t ah[4], al[4];
            {
                const __nv_bfloat16* pa = sAh + (wm * 16 + lg) * SA + kb + lt * 2;
                ah[0] = *reinterpret_cast<const uint32_t*>(pa);
                ah[1] = *reinterpret_cast<const uint32_t*>(pa + 8 * SA);
                ah[2] = *reinterpret_cast<const uint32_t*>(pa + 8);
                ah[3] = *reinterpret_cast<const uint32_t*>(pa + 8 * SA + 8);
                const __nv_bfloat16* pl = sAl + (wm * 16 + lg) * SA + kb + lt * 2;
                al[0] = *reinterpret_cast<const uint32_t*>(pl);
                al[1] = *reinterpret_cast<const uint32_t*>(pl + 8 * SA);
                al[2] = *reinterpret_cast<const uint32_t*>(pl + 8);
                al[3] = *reinterpret_cast<const uint32_t*>(pl + 8 * SA + 8);
            }
#pragma unroll
            for (int f = 0; f < 10; f++) {
                const int rowb = wn * 80 + f * 8 + lg;
                uint32_t bh[2], bl[2];
                const __nv_bfloat16* pb = sBh + rowb * SA + kb + lt * 2;
                bh[0] = *reinterpret_cast<const uint32_t*>(pb);
                bh[1] = *reinterpret_cast<const uint32_t*>(pb + 8);
                const __nv_bfloat16* pbl = sBl + rowb * SA + kb + lt * 2;
                bl[0] = *reinterpret_cast<const uint32_t*>(pbl);
                bl[1] = *reinterpret_cast<const uint32_t*>(pbl + 8);
                mma16816(acc[f], ah, bh);
                mma16816(acc[f], ah, bl);
                mma16816(acc[f], al, bh);
            }
        }
        __syncthreads();
    }

    // epilogue: Spart[ks][b][nu]
    float* base = g_Spart + (size_t)ks * (B_ * NUU);
    const int r0 = m0 + wm * 16 + lg;
#pragma unroll
    for (int f = 0; f < 10; f++) {
        const int nu = wn * 80 + f * 8 + lt * 2;
        *reinterpret_cast<float2*>(base + (size_t)r0 * NUU + nu)       = make_float2(acc[f][0], acc[f][1]);
        *reinterpret_cast<float2*>(base + (size_t)(r0 + 8) * NUU + nu) = make_float2(acc[f][2], acc[f][3]);
    }
}

// ---------------------------------------------------------------------------
// GEMM2 (HMMA): Gkn[k][nu] = sum_b Xt[k][b] * Vt[nu][b].
// grid 72 (128 k-rows each), 512 threads (16 warps: wm 0..7, wn 0..1).
// ---------------------------------------------------------------------------
#define G2_SMEM ((128*SA*2 + 160*SA*2) * 2)  // = 82944

__global__ void __launch_bounds__(512) k_hmma2() {
    extern __shared__ __nv_bfloat16 sm[];
    __nv_bfloat16* sAh = sm;
    __nv_bfloat16* sAl = sAh + 128 * SA;
    __nv_bfloat16* sBh = sAl + 128 * SA;
    __nv_bfloat16* sBl = sBh + 160 * SA;

    const int k0 = blockIdx.x * 128;
    const int tid = threadIdx.x;
    const int warp = tid >> 5, lane = tid & 31;
    const int wm = warp >> 1, wn = warp & 1;
    const int lg = lane >> 2, lt = lane & 3;

    float acc[10][4];
#pragma unroll
    for (int f = 0; f < 10; f++)
#pragma unroll
        for (int q = 0; q < 4; q++) acc[f][q] = 0.0f;

    for (int c4 = 0; c4 < 4; ++c4) {
        const int col = c4 * 64;
#pragma unroll
        for (int t = 0; t < 2; t++) {
            int idx = tid + t * 512;
            int r = idx >> 3, q = idx & 7;
            const size_t g = (size_t)(k0 + r) * B_ + col + q * 8;
            *reinterpret_cast<uint4*>(sAh + r * SA + q * 8) = *reinterpret_cast<const uint4*>(g_xth + g);
            *reinterpret_cast<uint4*>(sAl + r * SA + q * 8) = *reinterpret_cast<const uint4*>(g_xtl + g);
        }
#pragma unroll
        for (int t = 0; t < 3; t++) {
            int idx = tid + t * 512;
            if (idx < 1280) {
                int r = idx >> 3, q = idx & 7;
                const size_t g = (size_t)r * B_ + col + q * 8;
                *reinterpret_cast<uint4*>(sBh + r * SA + q * 8) = *reinterpret_cast<const uint4*>(g_Vth + g);
                *reinterpret_cast<uint4*>(sBl + r * SA + q * 8) = *reinterpret_cast<const uint4*>(g_Vtl + g);
            }
        }
        __syncthreads();

#pragma unroll
        for (int kk = 0; kk < 4; kk++) {
            const int kb = kk * 16;
            uint32_t ah[4], al[4];
            {
                const __nv_bfloat16* pa = sAh + (wm * 16 + lg) * SA + kb + lt * 2;
                ah[0] = *reinterpret_cast<const uint32_t*>(pa);
                ah[1] = *reinterpret_cast<const uint32_t*>(pa + 8 * SA);
                ah[2] = *reinterpret_cast<const uint32_t*>(pa + 8);
                ah[3] = *reinterpret_cast<const uint32_t*>(pa + 8 * SA + 8);
                const __nv_bfloat16* pl = sAl + (wm * 16 + lg) * SA + kb + lt * 2;
                al[0] = *reinterpret_cast<const uint32_t*>(pl);
                al[1] = *reinterpret_cast<const uint32_t*>(pl + 8 * SA);
                al[2] = *reinterpret_cast<const uint32_t*>(pl + 8);
                al[3] = *reinterpret_cast<const uint32_t*>(pl + 8 * SA + 8);
            }
#pragma unroll
            for (int f = 0; f < 10; f++) {
                const int rowb = wn * 80 + f * 8 + lg;
                uint32_t bh[2], bl[2];
                const __nv_bfloat16* pb = sBh + rowb * SA + kb + lt * 2;
                bh[0] = *reinterpret_cast<const uint32_t*>(pb);
                bh[1] = *reinterpret_cast<const uint32_t*>(pb + 8);
                const __nv_bfloat16* pbl = sBl + rowb * SA + kb + lt * 2;
                bl[0] = *reinterpret_cast<const uint32_t*>(pbl);
                bl[1] = *reinterpret_cast<const uint32_t*>(pbl + 8);
                mma16816(acc[f], ah, bh);
                mma16816(acc[f], ah, bl);
                mma16816(acc[f], al, bh);
            }
        }
        __syncthreads();
    }

    const int r0 = k0 + wm * 16 + lg;
#pragma unroll
    for (int f = 0; f < 10; f++) {
        const int nu = wn * 80 + f * 8 + lt * 2;
        *reinterpret_cast<float2*>(g_Gkn + (size_t)r0 * NUU + nu)       = make_float2(acc[f][0], acc[f][1]);
        *reinterpret_cast<float2*>(g_Gkn + (size_t)(r0 + 8) * NUU + nu) = make_float2(acc[f][2], acc[f][3]);
    }
}

// ---------------------------------------------------------------------------
// k_squash: reduce split-K, squash; emit bf16-split V^T or final output
// ---------------------------------------------------------------------------
__global__ void k_squash(float* __restrict__ out, int final_iter) {
    const int b = blockIdx.x;
    const int t = threadIdx.x;      // t = n*16 + u
    float s = 0.0f;
#pragma unroll 4
    for (int ks = 0; ks < KSPLIT; ks++)
        s += g_Spart[(size_t)ks * (B_ * NUU) + b * NUU + t];

    __shared__ float sq[NUU];
    __shared__ float mag[US];
    sq[t] = s * s;
    __syncthreads();
    if (t < US) {
        float m = 0.0f;
#pragma unroll
        for (int n = 0; n < NU_; n++) m += sq[n * US + t];
        mag[t] = m;
    }
    __syncthreads();
    float m = mag[t & 15];
    float v = s * (m / ((1.0f + m) * sqrtf(m)));
    if (final_iter) {
        out[b * NUU + t] = v;
    } else {
        __nv_bfloat16 h = __float2bfloat16_rn(v);
        __nv_bfloat16 l = __float2bfloat16_rn(v - __bfloat162float(h));
        g_Vth[t * B_ + b] = h;
        g_Vtl[t * B_ + b] = l;
    }
}

// ---------------------------------------------------------------------------
// k_bupdate: logits[j,n] += (1/B) sum_{i,u} Wkn[k][nu]*Gkn[k][nu], k=i*IC+j.
// grid 1152, 128 threads (i x u).
// ---------------------------------------------------------------------------
__global__ void k_bupdate() {
    const int j = blockIdx.x;
    const int t = threadIdx.x;
    const int i = t >> 4;
    const int u = t & 15;
    const size_t k = (size_t)i * IC + j;

    float part[NU_];
#pragma unroll
    for (int n = 0; n < NU_; n++) {
        int nu = n * US + u;
        part[n] = g_Wkn[k * NUU + nu] * g_Gkn[k * NUU + nu];
    }
#pragma unroll
    for (int off = 16; off; off >>= 1)
#pragma unroll
        for (int n = 0; n < NU_; n++)
            part[n] += __shfl_down_sync(0xffffffffu, part[n], off);

    __shared__ float red[NU_][4];
    int warp = t >> 5, lane = t & 31;
    if (lane == 0)
#pragma unroll
        for (int n = 0; n < NU_; n++) red[n][warp] = part[n];
    __syncthreads();
    if (t < NU_) {
        float d = red[t][0] + red[t][1] + red[t][2] + red[t][3];
        g_logits[j * NU_ + t] += d * (1.0f / (float)B_);
    }
}

// ---------------------------------------------------------------------------
// k_softmax over j for each n -> g_ct[n][j]. 1 block, 10 warps
// ---------------------------------------------------------------------------
__global__ void k_softmax() {
    const int t = threadIdx.x;
    const int n = t >> 5;
    const int lane = t & 31;
    float vals[36];
    float mx = -1e30f;
#pragma unroll
    for (int it = 0; it < 36; it++) {
        int j = lane + it * 32;
        vals[it] = g_logits[j * NU_ + n];
        mx = fmaxf(mx, vals[it]);
    }
#pragma unroll
    for (int off = 16; off; off >>= 1)
        mx = fmaxf(mx, __shfl_xor_sync(0xffffffffu, mx, off));
    float sum = 0.0f;
#pragma unroll
    for (int it = 0; it < 36; it++) { vals[it] = expf(vals[it] - mx); sum += vals[it]; }
#pragma unroll
    for (int off = 16; off; off >>= 1)
        sum += __shfl_xor_sync(0xffffffffu, sum, off);
    float inv = 1.0f / sum;
#pragma unroll
    for (int it = 0; it < 36; it++) {
        int j = lane + it * 32;
        g_ct[n * IC + j] = vals[it] * inv;
    }
}

// ---------------------------------------------------------------------------
extern "C" void kernel_launch(void* const* d_in, const int* in_sizes, int n_in,
                              void* d_out, int out_size) {
    const float* x = (const float*)d_in[0];   // [256, 8, 1152]
    const float* W = (const float*)d_in[1];   // [1152, 10, 16, 8]
    float* out = (float*)d_out;

    cudaFuncSetAttribute(k_hmma1, cudaFuncAttributeMaxDynamicSharedMemorySize, G1_SMEM);
    cudaFuncSetAttribute(k_hmma2, cudaFuncAttributeMaxDynamicSharedMemorySize, G2_SMEM);

    k_prex<<<dim3(KTOT / 64, B_ / 64), 256>>>(x);
    k_pre_w<<<IC / 8, 256>>>(W);

    for (int iter = 0; iter < 2; iter++) {
        k_scale<<<NUU, 256>>>();
        k_hmma1<<<4 * KSPLIT, 256, G1_SMEM>>>();
        k_squash<<<B_, NUU>>>(nullptr, 0);
        k_hmma2<<<KTOT / 128, 512, G2_SMEM>>>();
        k_bupdate<<<IC, 128>>>();
        k_softmax<<<1, 320>>>();
    }
    k_scale<<<NUU, 256>>>();
    k_hmma1<<<4 * KSPLIT, 256, G1_SMEM>>>();
    k_squash<<<B_, NUU>>>(out, 1);
}

// round 4
// speedup vs baseline: 1.8946x; 1.2055x over previous
#include <cuda_runtime.h>
#include <cuda_bf16.h>
#include <math.h>
#include <stdint.h>

// Problem constants
#define B_    256
#define IC    1152
#define NU_   10
#define US    16
#define IU    8
#define NUU   160       // NU_*US
#define KTOT  9216      // IU*IC
#define KSPLIT 36
#define SA    72        // smem row stride (bf16): 144B -> bank stride 4 mod 32, LDSM conflict-free

// ---------------- device scratch ----------------
__device__ __align__(128) __nv_bfloat16 g_xh [B_ * KTOT];
__device__ __align__(128) __nv_bfloat16 g_xl [B_ * KTOT];
__device__ __align__(128) __nv_bfloat16 g_xth[KTOT * B_];
__device__ __align__(128) __nv_bfloat16 g_xtl[KTOT * B_];
__device__ __align__(128) float g_Wnk[NUU * KTOT];
__device__ __align__(128) float g_Wkn[KTOT * NUU];
__device__ __align__(128) __nv_bfloat16 g_SWth[NUU * KTOT];
__device__ __align__(128) __nv_bfloat16 g_SWtl[NUU * KTOT];
__device__ __align__(128) __nv_bfloat16 g_Vth[NUU * B_];
__device__ __align__(128) __nv_bfloat16 g_Vtl[NUU * B_];
__device__ __align__(128) float g_Spart[KSPLIT * B_ * NUU];
__device__ __align__(128) float g_Gkn[2 * KTOT * NUU];     // 2 batch-split partials
__device__ float g_logits[IC * NU_];
__device__ float g_ct[NU_ * IC];

// ---------------- asm helpers ----------------
__device__ __forceinline__ uint32_t smem_to_u32(const void* p) {
    uint32_t a;
    asm("{ .reg .u64 t; cvta.to.shared.u64 t, %1; cvt.u32.u64 %0, t; }" : "=r"(a) : "l"(p));
    return a;
}
__device__ __forceinline__ void cpasync(uint32_t d, const void* g) {
    asm volatile("cp.async.cg.shared.global [%0], [%1], 16;" :: "r"(d), "l"(g));
}
#define CP_COMMIT() asm volatile("cp.async.commit_group;" ::: "memory")
#define CP_WAIT(n)  asm volatile("cp.async.wait_group %0;" :: "n"(n) : "memory")

__device__ __forceinline__ void ldsm_x4(uint32_t* r, uint32_t addr) {
    asm volatile("ldmatrix.sync.aligned.m8n8.x4.shared.b16 {%0,%1,%2,%3}, [%4];"
                 : "=r"(r[0]), "=r"(r[1]), "=r"(r[2]), "=r"(r[3]) : "r"(addr));
}
__device__ __forceinline__ void mma4(float* c, const uint32_t* a, uint32_t b0, uint32_t b1) {
    asm volatile("mma.sync.aligned.m16n8k16.row.col.f32.bf16.bf16.f32 "
        "{%0,%1,%2,%3}, {%4,%5,%6,%7}, {%8,%9}, {%0,%1,%2,%3};"
        : "+f"(c[0]), "+f"(c[1]), "+f"(c[2]), "+f"(c[3])
        : "r"(a[0]), "r"(a[1]), "r"(a[2]), "r"(a[3]), "r"(b0), "r"(b1));
}

// Shared compute: one 64-col K-chunk, 3-pass bf16-split, 10 n-frags per warp.
// aH/aL/bH/bL = smem u32 base addrs of the 4 sub-tiles in current buffer.
__device__ __forceinline__ void compute_chunk(uint32_t aH, uint32_t aL,
                                              uint32_t bH, uint32_t bL,
                                              int aRowByte, int bRowByte0,
                                              float acc[10][4]) {
#pragma unroll
    for (int kk = 0; kk < 4; kk++) {
        const int kb2 = kk * 32;              // 16 elems * 2B
        uint32_t ah[4], al[4];
        ldsm_x4(ah, aH + aRowByte + kb2);
        ldsm_x4(al, aL + aRowByte + kb2);
#pragma unroll
        for (int fp = 0; fp < 5; fp++) {
            const int boff = bRowByte0 + fp * (16 * SA * 2) + kb2;
            uint32_t bh[4], bl[4];
            ldsm_x4(bh, bH + boff);
            ldsm_x4(bl, bL + boff);
            mma4(acc[2 * fp],     ah, bh[0], bh[2]);
            mma4(acc[2 * fp],     ah, bl[0], bl[2]);
            mma4(acc[2 * fp],     al, bh[0], bh[2]);
            mma4(acc[2 * fp + 1], ah, bh[1], bh[3]);
            mma4(acc[2 * fp + 1], ah, bl[1], bl[3]);
            mma4(acc[2 * fp + 1], al, bh[1], bh[3]);
        }
    }
}

// ---------------------------------------------------------------------------
// k_prex: split x -> bf16 hi/lo, row-major and transposed. grid (144,4)x256
// ---------------------------------------------------------------------------
__global__ void k_prex(const float* __restrict__ x) {
    __shared__ unsigned sh[64][65];
    const int k0 = blockIdx.x * 64, b0 = blockIdx.y * 64;
    const int tid = threadIdx.x;
#pragma unroll
    for (int i = 0; i < 16; i++) {
        int idx = tid + i * 256;
        int r = idx >> 6, c = idx & 63;
        size_t g = (size_t)(b0 + r) * KTOT + k0 + c;
        float v = x[g];
        __nv_bfloat16 h = __float2bfloat16_rn(v);
        __nv_bfloat16 l = __float2bfloat16_rn(v - __bfloat162float(h));
        g_xh[g] = h; g_xl[g] = l;
        sh[r][c] = ((unsigned)__bfloat16_as_ushort(l) << 16) | (unsigned)__bfloat16_as_ushort(h);
    }
    __syncthreads();
#pragma unroll
    for (int i = 0; i < 16; i++) {
        int idx = tid + i * 256;
        int rr = idx >> 6, cc = idx & 63;
        unsigned p = sh[cc][rr];
        size_t g = (size_t)(k0 + rr) * B_ + b0 + cc;
        g_xth[g] = __ushort_as_bfloat16((unsigned short)(p & 0xFFFF));
        g_xtl[g] = __ushort_as_bfloat16((unsigned short)(p >> 16));
    }
}

// ---------------------------------------------------------------------------
// k_pre_w: W[j,n,u,i] -> Wnk[nu][k], Wkn[k][nu]; init logits/ct. grid 144x256
// ---------------------------------------------------------------------------
__global__ void k_pre_w(const float* __restrict__ W) {
    __shared__ float sm[8 * 1281];
    const int j0 = blockIdx.x * 8;
    const int tid = threadIdx.x;
#pragma unroll
    for (int i = 0; i < 40; i++) {
        int idx = tid + i * 256;
        int jl = idx / 1280, rem = idx - jl * 1280;
        sm[jl * 1281 + rem] = W[(size_t)(j0 + jl) * 1280 + rem];
    }
    __syncthreads();
#pragma unroll
    for (int t = 0; t < 40; t++) {
        int idx = tid + t * 256;                 // = nu*64 + ii*8 + jl
        int jl = idx & 7, ii = (idx >> 3) & 7, nu = idx >> 6;
        g_Wnk[(size_t)nu * KTOT + ii * IC + j0 + jl] = sm[jl * 1281 + nu * 8 + ii];
    }
#pragma unroll
    for (int t = 0; t < 40; t++) {
        int idx = tid + t * 256;                 // = (ii*8 + jl)*160 + nu
        int nu = idx % 160, rest = idx / 160;
        int jl = rest & 7, ii = rest >> 3;
        g_Wkn[(size_t)(ii * IC + j0 + jl) * NUU + nu] = sm[jl * 1281 + nu * 8 + ii];
    }
    int gidx = blockIdx.x * 256 + tid;
    if (gidx < IC * NU_) { g_logits[gidx] = 0.0f; g_ct[gidx] = 1.0f / (float)IC; }
}

// ---------------------------------------------------------------------------
// k_scale: SWt_{hi,lo}[nu][k] = split(Wnk[nu][k] * c[n][j]). grid 160x256
// ---------------------------------------------------------------------------
__global__ void k_scale() {
    __shared__ float cs[IC];
    const int nu = blockIdx.x;
    const int n = nu >> 4;
    const int tid = threadIdx.x;
    for (int t = tid; t < IC; t += 256) cs[t] = g_ct[n * IC + t];
    __syncthreads();
#pragma unroll
    for (int i = 0; i < 9; i++) {
        int e4 = tid + i * 256;
        int k = e4 * 4;
        int j = k % IC;
        float4 w = *reinterpret_cast<const float4*>(g_Wnk + (size_t)nu * KTOT + k);
        float v0 = w.x * cs[j], v1 = w.y * cs[j + 1], v2 = w.z * cs[j + 2], v3 = w.w * cs[j + 3];
        __nv_bfloat16 h0 = __float2bfloat16_rn(v0), h1 = __float2bfloat16_rn(v1);
        __nv_bfloat16 h2 = __float2bfloat16_rn(v2), h3 = __float2bfloat16_rn(v3);
        __nv_bfloat16 l0 = __float2bfloat16_rn(v0 - __bfloat162float(h0));
        __nv_bfloat16 l1 = __float2bfloat16_rn(v1 - __bfloat162float(h1));
        __nv_bfloat16 l2 = __float2bfloat16_rn(v2 - __bfloat162float(h2));
        __nv_bfloat16 l3 = __float2bfloat16_rn(v3 - __bfloat162float(h3));
        uint2 ph, pl;
        ph.x = ((unsigned)__bfloat16_as_ushort(h1) << 16) | __bfloat16_as_ushort(h0);
        ph.y = ((unsigned)__bfloat16_as_ushort(h3) << 16) | __bfloat16_as_ushort(h2);
        pl.x = ((unsigned)__bfloat16_as_ushort(l1) << 16) | __bfloat16_as_ushort(l0);
        pl.y = ((unsigned)__bfloat16_as_ushort(l3) << 16) | __bfloat16_as_ushort(l2);
        *reinterpret_cast<uint2*>(g_SWth + (size_t)nu * KTOT + k) = ph;
        *reinterpret_cast<uint2*>(g_SWtl + (size_t)nu * KTOT + k) = pl;
    }
}

// ---------------------------------------------------------------------------
// GEMM1: Spart[ks][b-tile 64][nu] = X * (c.W)^T over 256-k chunk. grid 144x256.
// Buffer layout (bf16 elems): [aH 64*SA][aL 64*SA][bH 160*SA][bL 160*SA]
// ---------------------------------------------------------------------------
#define BUF1 (448 * SA * 2)          // 64512 B
#define G1_SMEM (2 * BUF1)           // 129024

__device__ __forceinline__ void g1_load(uint32_t sb, int m0, int col, int tid) {
#pragma unroll
    for (int t = 0; t < 2; t++) {
        int idx = tid + t * 256;
        int r = idx >> 3, q = idx & 7;
        uint32_t d = sb + (uint32_t)(r * SA + q * 8) * 2;
        size_t g = (size_t)(m0 + r) * KTOT + col + q * 8;
        cpasync(d, g_xh + g);
        cpasync(d + 64 * SA * 2, g_xl + g);
    }
#pragma unroll
    for (int t = 0; t < 5; t++) {
        int idx = tid + t * 256;
        int r = idx >> 3, q = idx & 7;
        uint32_t d = sb + 128 * SA * 2 + (uint32_t)(r * SA + q * 8) * 2;
        size_t g = (size_t)r * KTOT + col + q * 8;
        cpasync(d, g_SWth + g);
        cpasync(d + 160 * SA * 2, g_SWtl + g);
    }
}

__global__ void __launch_bounds__(256) k_hmma1() {
    extern __shared__ char sm[];
    const int mt = blockIdx.x & 3, ks = blockIdx.x >> 2;
    const int m0 = mt * 64, kbase = ks * 256;
    const int tid = threadIdx.x, warp = tid >> 5, lane = tid & 31;
    const int wm = warp & 3, wn = warp >> 2;
    const int lg = lane >> 2, lt = lane & 3;
    const uint32_t sb = smem_to_u32(sm);

    const int aRowByte = ((wm * 16 + (lane & 15)) * SA + (lane >> 4) * 8) * 2;
    const int bRowByte0 = ((wn * 80 + (lane & 15)) * SA + (lane >> 4) * 8) * 2;

    float acc[10][4];
#pragma unroll
    for (int f = 0; f < 10; f++)
#pragma unroll
        for (int q = 0; q < 4; q++) acc[f][q] = 0.0f;

    g1_load(sb,        m0, kbase,      tid); CP_COMMIT();
    g1_load(sb + BUF1, m0, kbase + 64, tid); CP_COMMIT();

#define G1_BUFS(base) (base), (base) + 64 * SA * 2, (base) + 128 * SA * 2, (base) + 288 * SA * 2

    CP_WAIT(1); __syncthreads();
    compute_chunk(G1_BUFS(sb), aRowByte, bRowByte0, acc);
    __syncthreads();
    g1_load(sb, m0, kbase + 128, tid); CP_COMMIT();

    CP_WAIT(1); __syncthreads();
    compute_chunk(G1_BUFS(sb + BUF1), aRowByte, bRowByte0, acc);
    __syncthreads();
    g1_load(sb + BUF1, m0, kbase + 192, tid); CP_COMMIT();

    CP_WAIT(1); __syncthreads();
    compute_chunk(G1_BUFS(sb), aRowByte, bRowByte0, acc);

    CP_WAIT(0); __syncthreads();
    compute_chunk(G1_BUFS(sb + BUF1), aRowByte, bRowByte0, acc);

    float* base = g_Spart + (size_t)ks * (B_ * NUU);
    const int r0 = m0 + wm * 16 + lg;
#pragma unroll
    for (int f = 0; f < 10; f++) {
        const int nu = wn * 80 + f * 8 + lt * 2;
        *reinterpret_cast<float2*>(base + (size_t)r0 * NUU + nu)       = make_float2(acc[f][0], acc[f][1]);
        *reinterpret_cast<float2*>(base + (size_t)(r0 + 8) * NUU + nu) = make_float2(acc[f][2], acc[f][3]);
    }
}

// ---------------------------------------------------------------------------
// GEMM2: Gkn[ksp][k-tile 128][nu] = sum_{b in half} Xt[k][b] * Vt[nu][b].
// grid 144 (= k-tile 0..71 x bsplit 0..1), 512 threads. K per CTA = 128 (2 chunks).
// Buffer layout: [aH 128*SA][aL 128*SA][bH 160*SA][bL 160*SA]
// ---------------------------------------------------------------------------
#define BUF2 (576 * SA * 2)          // 82944 B
#define G2_SMEM (2 * BUF2)           // 165888

__device__ __forceinline__ void g2_load(uint32_t sb, int k0, int col, int tid) {
#pragma unroll
    for (int t = 0; t < 2; t++) {
        int idx = tid + t * 512;
        int r = idx >> 3, q = idx & 7;
        uint32_t d = sb + (uint32_t)(r * SA + q * 8) * 2;
        size_t g = (size_t)(k0 + r) * B_ + col + q * 8;
        cpasync(d, g_xth + g);
        cpasync(d + 128 * SA * 2, g_xtl + g);
    }
#pragma unroll
    for (int t = 0; t < 3; t++) {
        int idx = tid + t * 512;
        if (idx < 1280) {
            int r = idx >> 3, q = idx & 7;
            uint32_t d = sb + 256 * SA * 2 + (uint32_t)(r * SA + q * 8) * 2;
            size_t g = (size_t)r * B_ + col + q * 8;
            cpasync(d, g_Vth + g);
            cpasync(d + 160 * SA * 2, g_Vtl + g);
        }
    }
}

__global__ void __launch_bounds__(512) k_hmma2() {
    extern __shared__ char sm[];
    const int ksp = blockIdx.x & 1;
    const int k0 = (blockIdx.x >> 1) * 128;
    const int col0 = ksp * 128;
    const int tid = threadIdx.x, warp = tid >> 5, lane = tid & 31;
    const int wm = warp >> 1, wn = warp & 1;
    const int lg = lane >> 2, lt = lane & 3;
    const uint32_t sb = smem_to_u32(sm);

    const int aRowByte = ((wm * 16 + (lane & 15)) * SA + (lane >> 4) * 8) * 2;
    const int bRowByte0 = ((wn * 80 + (lane & 15)) * SA + (lane >> 4) * 8) * 2;

    float acc[10][4];
#pragma unroll
    for (int f = 0; f < 10; f++)
#pragma unroll
        for (int q = 0; q < 4; q++) acc[f][q] = 0.0f;

    g2_load(sb,        k0, col0,      tid); CP_COMMIT();
    g2_load(sb + BUF2, k0, col0 + 64, tid); CP_COMMIT();

#define G2_BUFS(base) (base), (base) + 128 * SA * 2, (base) + 256 * SA * 2, (base) + 416 * SA * 2

    CP_WAIT(1); __syncthreads();
    compute_chunk(G2_BUFS(sb), aRowByte, bRowByte0, acc);

    CP_WAIT(0); __syncthreads();
    compute_chunk(G2_BUFS(sb + BUF2), aRowByte, bRowByte0, acc);

    float* gout = g_Gkn + (size_t)ksp * KTOT * NUU;
    const int r0 = k0 + wm * 16 + lg;
#pragma unroll
    for (int f = 0; f < 10; f++) {
        const int nu = wn * 80 + f * 8 + lt * 2;
        *reinterpret_cast<float2*>(gout + (size_t)r0 * NUU + nu)       = make_float2(acc[f][0], acc[f][1]);
        *reinterpret_cast<float2*>(gout + (size_t)(r0 + 8) * NUU + nu) = make_float2(acc[f][2], acc[f][3]);
    }
}

// ---------------------------------------------------------------------------
// k_squash: reduce split-K, squash; emit bf16-split V^T or final output
// ---------------------------------------------------------------------------
__global__ void k_squash(float* __restrict__ out, int final_iter) {
    const int b = blockIdx.x;
    const int t = threadIdx.x;      // t = n*16 + u
    float s = 0.0f;
#pragma unroll 4
    for (int ks = 0; ks < KSPLIT; ks++)
        s += g_Spart[(size_t)ks * (B_ * NUU) + b * NUU + t];

    __shared__ float sq[NUU];
    __shared__ float mag[US];
    sq[t] = s * s;
    __syncthreads();
    if (t < US) {
        float m = 0.0f;
#pragma unroll
        for (int n = 0; n < NU_; n++) m += sq[n * US + t];
        mag[t] = m;
    }
    __syncthreads();
    float m = mag[t & 15];
    float v = s * (m / ((1.0f + m) * sqrtf(m)));
    if (final_iter) {
        out[b * NUU + t] = v;
    } else {
        __nv_bfloat16 h = __float2bfloat16_rn(v);
        __nv_bfloat16 l = __float2bfloat16_rn(v - __bfloat162float(h));
        g_Vth[t * B_ + b] = h;
        g_Vtl[t * B_ + b] = l;
    }
}

// ---------------------------------------------------------------------------
// k_bupdate: logits[j,n] += (1/B) sum_{i,u} Wkn[k][nu]*(G0+G1)[k][nu], k=i*IC+j
// ---------------------------------------------------------------------------
__global__ void k_bupdate() {
    const int j = blockIdx.x;
    const int t = threadIdx.x;
    const int i = t >> 4;
    const int u = t & 15;
    const size_t k = (size_t)i * IC + j;

    float part[NU_];
#pragma unroll
    for (int n = 0; n < NU_; n++) {
        size_t idx = k * NUU + n * US + u;
        part[n] = g_Wkn[idx] * (g_Gkn[idx] + g_Gkn[(size_t)KTOT * NUU + idx]);
    }
#pragma unroll
    for (int off = 16; off; off >>= 1)
#pragma unroll
        for (int n = 0; n < NU_; n++)
            part[n] += __shfl_down_sync(0xffffffffu, part[n], off);

    __shared__ float red[NU_][4];
    int warp = t >> 5, lane = t & 31;
    if (lane == 0)
#pragma unroll
        for (int n = 0; n < NU_; n++) red[n][warp] = part[n];
    __syncthreads();
    if (t < NU_) {
        float d = red[t][0] + red[t][1] + red[t][2] + red[t][3];
        g_logits[j * NU_ + t] += d * (1.0f / (float)B_);
    }
}

// ---------------------------------------------------------------------------
// k_softmax over j for each n -> g_ct[n][j]. 1 block, 10 warps
// ---------------------------------------------------------------------------
__global__ void k_softmax() {
    const int t = threadIdx.x;
    const int n = t >> 5;
    const int lane = t & 31;
    float vals[36];
    float mx = -1e30f;
#pragma unroll
    for (int it = 0; it < 36; it++) {
        int j = lane + it * 32;
        vals[it] = g_logits[j * NU_ + n];
        mx = fmaxf(mx, vals[it]);
    }
#pragma unroll
    for (int off = 16; off; off >>= 1)
        mx = fmaxf(mx, __shfl_xor_sync(0xffffffffu, mx, off));
    float sum = 0.0f;
#pragma unroll
    for (int it = 0; it < 36; it++) { vals[it] = expf(vals[it] - mx); sum += vals[it]; }
#pragma unroll
    for (int off = 16; off; off >>= 1)
        sum += __shfl_xor_sync(0xffffffffu, sum, off);
    float inv = 1.0f / sum;
#pragma unroll
    for (int it = 0; it < 36; it++) {
        int j = lane + it * 32;
        g_ct[n * IC + j] = vals[it] * inv;
    }
}

// ---------------------------------------------------------------------------
extern "C" void kernel_launch(void* const* d_in, const int* in_sizes, int n_in,
                              void* d_out, int out_size) {
    const float* x = (const float*)d_in[0];   // [256, 8, 1152]
    const float* W = (const float*)d_in[1];   // [1152, 10, 16, 8]
    float* out = (float*)d_out;

    cudaFuncSetAttribute(k_hmma1, cudaFuncAttributeMaxDynamicSharedMemorySize, G1_SMEM);
    cudaFuncSetAttribute(k_hmma2, cudaFuncAttributeMaxDynamicSharedMemorySize, G2_SMEM);

    k_prex<<<dim3(KTOT / 64, B_ / 64), 256>>>(x);
    k_pre_w<<<IC / 8, 256>>>(W);

    for (int iter = 0; iter < 2; iter++) {
        k_scale<<<NUU, 256>>>();
        k_hmma1<<<4 * KSPLIT, 256, G1_SMEM>>>();
        k_squash<<<B_, NUU>>>(nullptr, 0);
        k_hmma2<<<144, 512, G2_SMEM>>>();
        k_bupdate<<<IC, 128>>>();
        k_softmax<<<1, 320>>>();
    }
    k_scale<<<NUU, 256>>>();
    k_hmma1<<<4 * KSPLIT, 256, G1_SMEM>>>();
    k_squash<<<B_, NUU>>>(out, 1);
}